// round 14
// baseline (speedup 1.0000x reference)
#include <cuda_runtime.h>
#include <cstdint>
#include <cstddef>

// BacklashNet chunk-parallel scan: warp-decoupled SMEM staging, interval collapse.
//   lo = fl(fl(m_lo*x) + fl(m_lo*c_lo)), upx = fl(m_up*x), ub = fl(upx + k_up)
//   f1 = (prev >= lo);  f2 = (fl(prev - upx) <= k_up)
//   out = f1 ? (f2 ? fl(fl(lo+upx)+k_up) : lo) : (f2 ? ub : prev)
// Identity branch needs prev in (ub*, lo): interval-tracked until it provably
// collapses to one value -> chunk outputs become state-independent.
// Phase 1 runs a UNIFORM branch-free 8-step merged interval+concrete loop
// (divergence-free), then a uniform concrete loop for steps 8..15.

#define NT   512          // threads per block = chunks per row
#define CL   16           // steps per chunk (T = NT*CL = 8192)
#define PAD  20           // smem floats per chunk: 80B stride, 16B aligned;
                          //   conflict-free for 128-bit LDS/STS; slots [16..19]
#define WREG 512          // floats per warp region (32 lanes * CL)

struct Wt { float m_lo, m_up, k_lo, k_up; };

__device__ __forceinline__ uint32_t smem_u32(const void* p) {
    return (uint32_t)__cvta_generic_to_shared(p);
}
__device__ __forceinline__ void cp_async16(uint32_t dst, const float* src) {
    asm volatile("cp.async.ca.shared.global [%0], [%1], 16;\n" :: "r"(dst), "l"(src));
}

__device__ __forceinline__ bool f2_pred(float p, float upx, float k_up) {
    return __fadd_rn(p, -upx) <= k_up;          // fl(p - upx) <= k_up (monotone in p)
}
__device__ __forceinline__ void mkconst(const Wt& w, float xv,
                                        float& lo, float& upx, float& ub, float& v1) {
    float mlx = __fmul_rn(w.m_lo, xv);
    upx = __fmul_rn(w.m_up, xv);
    lo  = __fadd_rn(mlx, w.k_lo);
    ub  = __fadd_rn(upx, w.k_up);
    v1  = __fadd_rn(__fadd_rn(lo, upx), w.k_up); // reference's left-assoc sum
}
__device__ __forceinline__ float step1(float p, float lo, float upx, float ub,
                                       float v1, float k_up) {
    bool f1 = (p >= lo);
    bool f2 = f2_pred(p, upx, k_up);
    float a = f2 ? v1 : lo;
    float b = f2 ? ub : p;
    return f1 ? a : b;
}

__global__ __launch_bounds__(NT, 3)
void backlash_chunks(const float* __restrict__ x,
                     const float* __restrict__ p0,
                     const float* __restrict__ wv,
                     float* __restrict__ out, int T)
{
    __shared__ float s_buf[NT * PAD];   // chunk data + pad slots:
                                        //   xc[16]=cv  xc[17]=sx(int)  xc[18]=in

    const int k    = threadIdx.x;
    const int wid  = k >> 5;            // warp id (0..15)
    const int lane = k & 31;

    Wt w;
    w.m_lo = wv[0];
    w.m_up = wv[1];
    w.k_lo = __fmul_rn(w.m_lo, wv[2]);
    w.k_up = __fmul_rn(w.m_up, wv[3]);

    const size_t rowbase = (size_t)blockIdx.x * T;

    // ---- Warp-local coalesced staged load: warp w owns chunks [32w, 32w+32) ----
    {
        const float* src = x + rowbase + wid * WREG;
        const uint32_t sb = smem_u32(s_buf);
        #pragma unroll
        for (int i = 0; i < 4; ++i) {
            int tl = i * 128 + lane * 4;            // [0, 512) within warp region
            int c  = wid * 32 + (tl >> 4);
            int o  = tl & 15;
            cp_async16(sb + (uint32_t)(c * PAD + o) * 4u, src + tl);
        }
        asm volatile("cp.async.commit_group;\n" ::: "memory");
        asm volatile("cp.async.wait_group 0;\n" ::: "memory");
        __syncwarp();   // make cp.async data visible across the warp's lanes
    }

    float* xc = s_buf + k * PAD;        // this thread's chunk (in; becomes out)
    const float INF = __int_as_float(0x7f800000);

    // ---- Phase 1A: uniform branch-free merged interval+concrete, t = 0..7 ----
    float xs[8];
    {
        float4 q0 = *(const float4*)(xc + 0);
        float4 q1 = *(const float4*)(xc + 4);
        xs[0]=q0.x; xs[1]=q0.y; xs[2]=q0.z; xs[3]=q0.w;
        xs[4]=q1.x; xs[5]=q1.y; xs[6]=q1.z; xs[7]=q1.w;
    }

    float A = -INF, Bv = INF;
    float p = 0.0f;
    bool  done = false;
    int   s = CL;

    #pragma unroll
    for (int t = 0; t < 8; ++t) {
        float lo, upx, ub, v1;
        mkconst(w, xs[t], lo, upx, ub, v1);
        // Concrete candidate (used once done).
        float cand = step1(p, lo, upx, ub, v1, w.k_up);
        // Interval hull update (exact predicate evals at endpoints; ps is a
        // <=1-ulp conservative identity-hull top — can only over-keep: sound).
        float mAlo = fmaxf(A, lo);
        float ps   = fminf(Bv, lo);
        bool aL = (A < lo);
        bool c1 = (mAlo <= Bv) &&  f2_pred(mAlo, upx, w.k_up); // f1& f2 -> v1
        bool c2 = (Bv >= lo)   && !f2_pred(Bv,   upx, w.k_up); // f1&!f2 -> lo
        bool c3 = aL           &&  f2_pred(A,    upx, w.k_up); //!f1& f2 -> ub
        bool c4 = aL           && !f2_pred(ps,   upx, w.k_up); // identity
        float nA = INF, nB = -INF;
        if (c1) { nA = fminf(nA, v1); nB = fmaxf(nB, v1); }
        if (c2) { nA = fminf(nA, lo); nB = fmaxf(nB, lo); }
        if (c3) { nA = fminf(nA, ub); nB = fmaxf(nB, ub); }
        if (c4) { nA = fminf(nA, A);  nB = fmaxf(nB, ps); }
        bool newc = !done && (nA == nB);          // collapse at this step
        p = done ? cand : (newc ? nA : p);
        if (newc) s = t;
        if (!done) { A = nA; Bv = nB; }           // freeze hull after collapse
        bool str = done || newc;                  // t >= s for collapsed lanes
        done = str;
        if (str) xc[t] = p;                       // in-place output store
    }

    // ---- Rare tail: interval scan t = 8..15 for lanes not yet collapsed ----
    if (!done) {
        #pragma unroll 1
        for (int t4 = 8; t4 < CL && !done; t4 += 4) {
            float4 q = *(const float4*)(xc + t4);
            float xt[4] = {q.x, q.y, q.z, q.w};
            #pragma unroll
            for (int j = 0; j < 4; ++j) {
                if (!done) {
                    float lo, upx, ub, v1;
                    mkconst(w, xt[j], lo, upx, ub, v1);
                    float mAlo = fmaxf(A, lo);
                    float ps   = fminf(Bv, lo);
                    bool aL = (A < lo);
                    bool c1 = (mAlo <= Bv) &&  f2_pred(mAlo, upx, w.k_up);
                    bool c2 = (Bv >= lo)   && !f2_pred(Bv,   upx, w.k_up);
                    bool c3 = aL           &&  f2_pred(A,    upx, w.k_up);
                    bool c4 = aL           && !f2_pred(ps,   upx, w.k_up);
                    float nA = INF, nB = -INF;
                    if (c1) { nA = fminf(nA, v1); nB = fmaxf(nB, v1); }
                    if (c2) { nA = fminf(nA, lo); nB = fmaxf(nB, lo); }
                    if (c3) { nA = fminf(nA, ub); nB = fmaxf(nB, ub); }
                    if (c4) { nA = fminf(nA, A);  nB = fmaxf(nB, ps); }
                    A = nA; Bv = nB;
                    if (A == Bv) { done = true; p = A; s = t4 + j; }
                }
            }
        }
    }

    // ---- Phase 1C: uniform concrete scan t = 8..15 (guards cover tail lanes) ----
    #pragma unroll
    for (int g = 8; g < CL; g += 4) {
        float4 q = *(const float4*)(xc + g);
        float xg[4] = {q.x, q.y, q.z, q.w};
        float ov[4];
        #pragma unroll
        for (int j = 0; j < 4; ++j) {
            int t = g + j;
            float lo, upx, ub, v1;
            mkconst(w, xg[j], lo, upx, ub, v1);
            float cand = step1(p, lo, upx, ub, v1, w.k_up);
            p = (t > s) ? cand : p;       // t==s keeps collapse value; t<s: no-op
            ov[j] = p;
        }
        if (s <= g) {                     // common: whole group is output
            *(float4*)(xc + g) = make_float4(ov[0], ov[1], ov[2], ov[3]);
        } else {                          // rare tail lane: partial stores
            #pragma unroll
            for (int j = 0; j < 4; ++j)
                if (g + j >= s) xc[g + j] = ov[j];
        }
    }

    // ---- Phase 2: inter-chunk resolution (pad-slot side channel) ----
    xc[16] = p;                                  // collapsed end value
    reinterpret_cast<int*>(xc)[17] = s;          // collapse index
    bool all = (bool)__syncthreads_and((int)done);   // block-uniform barrier
    float pin;
    if (all) {
        pin = (k == 0) ? p0[blockIdx.x] : s_buf[(k - 1) * PAD + 16];
    } else {
        if (k == 0) {                             // rare serial fallback
            float prev = p0[blockIdx.x];
            for (int c = 0; c < NT; ++c) {
                float* xr = s_buf + c * PAD;
                xr[18] = prev;
                if (reinterpret_cast<int*>(xr)[17] < CL) {
                    prev = xr[16];
                } else {                          // chunk input untouched
                    for (int tt = 0; tt < CL; ++tt) {
                        float lo, upx, ub, v1;
                        mkconst(w, xr[tt], lo, upx, ub, v1);
                        prev = step1(prev, lo, upx, ub, v1, w.k_up);
                    }
                }
            }
        }
        __syncthreads();
        pin = xc[18];
    }

    // ---- Phase 3: replay pre-collapse prefix, vectorized SMEM access ----
    // Group loads are safe: elements with idx >= s are outputs, never consumed.
    #pragma unroll 1
    for (int t4 = 0; t4 < s; t4 += 4) {
        float4 q = *(const float4*)(xc + t4);
        float xt[4] = {q.x, q.y, q.z, q.w};
        float ov[4];
        #pragma unroll
        for (int j = 0; j < 4; ++j) {
            if (t4 + j < s) {
                float lo, upx, ub, v1;
                mkconst(w, xt[j], lo, upx, ub, v1);
                pin = step1(pin, lo, upx, ub, v1, w.k_up);
            }
            ov[j] = pin;              // idx >= s lanes: value unused
        }
        if (t4 + 4 <= s) {            // full group -> conflict-free STS.128
            *(float4*)(xc + t4) = make_float4(ov[0], ov[1], ov[2], ov[3]);
        } else {                      // final partial group -> scalar stores
            #pragma unroll
            for (int j = 0; j < 4; ++j)
                if (t4 + j < s) xc[t4 + j] = ov[j];
        }
    }

    // ---- Warp-local coalesced store: warp w's chunks are final once its own
    //      lanes finish phase 3 (no block barrier needed) ----
    __syncwarp();
    {
        float* dst = out + rowbase + wid * WREG;
        #pragma unroll
        for (int i = 0; i < 4; ++i) {
            int tl = i * 128 + lane * 4;
            int c  = wid * 32 + (tl >> 4);
            int o  = tl & 15;
            float4 v = *(const float4*)(s_buf + c * PAD + o);
            *(float4*)(dst + tl) = v;
        }
    }
}

extern "C" void kernel_launch(void* const* d_in, const int* in_sizes, int n_in,
                              void* d_out, int out_size)
{
    const float* x  = (const float*)d_in[0];  // (B, T, 1) fp32
    const float* p0 = (const float*)d_in[1];  // (B, 1, 1) fp32
    const float* wv = (const float*)d_in[2];  // (4,)      fp32
    float* out = (float*)d_out;

    const int B = in_sizes[1];      // 2048
    const int T = in_sizes[0] / B;  // 8192  (= NT * CL)

    backlash_chunks<<<B, NT>>>(x, p0, wv, out, T);
}

// round 16
// speedup vs baseline: 1.0166x; 1.0166x over previous
#include <cuda_runtime.h>
#include <cstdint>
#include <cstddef>

// BacklashNet chunk-parallel scan: warp-decoupled SMEM staging, interval collapse.
//   lo = fl(fl(m_lo*x) + fl(m_lo*c_lo)), upx = fl(m_up*x), ub = fl(upx + k_up)
//   f1 = (prev >= lo);  f2 = (fl(prev - upx) <= k_up)
//   out = f1 ? (f2 ? fl(fl(lo+upx)+k_up) : lo) : (f2 ? ub : prev)
// Identity branch needs prev in (ub*, lo): interval-tracked until it provably
// collapses to one value -> chunk outputs become state-independent.
// f2 is monotone non-increasing in p, so endpoint predicate evals reduce to
// three: f2(A), f2(Bv), f2(lo)  (exact identities, see phase 1a).

#define NT   512          // threads per block = chunks per row
#define CL   16           // steps per chunk (T = NT*CL = 8192)
#define PAD  20           // smem floats per chunk: 80B stride, 16B aligned;
                          //   conflict-free for 128-bit LDS/STS; slots [16..19]
#define WREG 512          // floats per warp region (32 lanes * CL)

struct Wt { float m_lo, m_up, k_lo, k_up; };

__device__ __forceinline__ uint32_t smem_u32(const void* p) {
    return (uint32_t)__cvta_generic_to_shared(p);
}
__device__ __forceinline__ void cp_async16(uint32_t dst, const float* src) {
    asm volatile("cp.async.ca.shared.global [%0], [%1], 16;\n" :: "r"(dst), "l"(src));
}

__device__ __forceinline__ bool f2_pred(float p, float upx, float k_up) {
    return __fadd_rn(p, -upx) <= k_up;          // fl(p - upx) <= k_up (monotone in p)
}
__device__ __forceinline__ void mkconst(const Wt& w, float xv,
                                        float& lo, float& upx, float& ub, float& v1) {
    float mlx = __fmul_rn(w.m_lo, xv);
    upx = __fmul_rn(w.m_up, xv);
    lo  = __fadd_rn(mlx, w.k_lo);
    ub  = __fadd_rn(upx, w.k_up);
    v1  = __fadd_rn(__fadd_rn(lo, upx), w.k_up); // reference's left-assoc sum
}
__device__ __forceinline__ float step1(float p, float lo, float upx, float ub,
                                       float v1, float k_up) {
    bool f1 = (p >= lo);
    bool f2 = f2_pred(p, upx, k_up);
    float a = f2 ? v1 : lo;
    float b = f2 ? ub : p;
    return f1 ? a : b;
}

__global__ __launch_bounds__(NT, 3)
void backlash_chunks(const float* __restrict__ x,
                     const float* __restrict__ p0,
                     const float* __restrict__ wv,
                     float* __restrict__ out, int T)
{
    __shared__ float s_buf[NT * PAD];   // chunk data + pad slots:
                                        //   xc[16]=cv  xc[17]=sx(int)  xc[18]=in

    const int k    = threadIdx.x;
    const int wid  = k >> 5;            // warp id (0..15)
    const int lane = k & 31;

    Wt w;
    w.m_lo = wv[0];
    w.m_up = wv[1];
    w.k_lo = __fmul_rn(w.m_lo, wv[2]);
    w.k_up = __fmul_rn(w.m_up, wv[3]);

    const size_t rowbase = (size_t)blockIdx.x * T;

    // Prefetch row-initial state early (hides DRAM/L2 latency that would
    // otherwise sit on warp 0's post-barrier critical path).
    float p0v = 0.0f;
    if (k == 0) p0v = __ldg(&p0[blockIdx.x]);

    // ---- Warp-local coalesced staged load: warp w owns chunks [32w, 32w+32) ----
    {
        const float* src = x + rowbase + wid * WREG;
        const uint32_t sb = smem_u32(s_buf);
        #pragma unroll
        for (int i = 0; i < 4; ++i) {
            int tl = i * 128 + lane * 4;            // [0, 512) within warp region
            int c  = wid * 32 + (tl >> 4);
            int o  = tl & 15;
            cp_async16(sb + (uint32_t)(c * PAD + o) * 4u, src + tl);
        }
        asm volatile("cp.async.commit_group;\n" ::: "memory");
        asm volatile("cp.async.wait_group 0;\n" ::: "memory");
        __syncwarp();   // make cp.async data visible across the warp's lanes
    }

    float* xc = s_buf + k * PAD;        // this thread's chunk (in; becomes out)
    const float INF = __int_as_float(0x7f800000);

    // ---- Phase 1a: interval scan until collapse (float4 group loads, no stores) ----
    float A = -INF, Bv = INF;
    float p = 0.0f;
    bool  done = false;
    int   s = CL;

    #pragma unroll 1
    for (int t4 = 0; t4 < CL && !done; t4 += 4) {
        float4 q = *(const float4*)(xc + t4);
        float xs[4] = {q.x, q.y, q.z, q.w};
        #pragma unroll
        for (int j = 0; j < 4; ++j) {
            if (!done) {
                float lo, upx, ub, v1;
                mkconst(w, xs[j], lo, upx, ub, v1);
                // Region reachability over [A,Bv]. f2 monotone non-increasing:
                //   f2(max(A,lo)) = f2A & f2lo ;  f2(min(Bv,lo)) = f2B | f2lo
                //   max(A,lo)<=Bv = (lo<=Bv)  [A<=Bv invariant: hull nonempty]
                // ps = fminf(Bv, lo): conservative (<=1 ulp) identity hull top;
                // survival test at ps can only over-keep (sound).
                bool f2A  = f2_pred(A,  upx, w.k_up);
                bool f2B  = f2_pred(Bv, upx, w.k_up);
                bool f2lo = f2_pred(lo, upx, w.k_up);
                bool aL   = (A < lo);
                float ps  = fminf(Bv, lo);
                bool c1 = (lo <= Bv) && f2A && f2lo;   // f1& f2 -> v1
                bool c2 = (Bv >= lo) && !f2B;          // f1&!f2 -> lo
                bool c3 = aL && f2A;                   //!f1& f2 -> ub
                bool c4 = aL && !f2B && !f2lo;         // identity survives
                float nA = INF, nB = -INF;
                if (c1) { nA = fminf(nA, v1); nB = fmaxf(nB, v1); }
                if (c2) { nA = fminf(nA, lo); nB = fmaxf(nB, lo); }
                if (c3) { nA = fminf(nA, ub); nB = fmaxf(nB, ub); }
                if (c4) { nA = fminf(nA, A);  nB = fmaxf(nB, ps); }
                A = nA; Bv = nB;
                if (A == Bv) { done = true; p = A; s = t4 + j; }
            }
        }
    }

    // ---- Phase 1b: concrete scan, in-place stores for t >= s ----
    // Partial group (contains s..): one conflict-free LDS.128, predicated scalar
    // stores only for indices in (s, group end). Inputs at idx < s stay intact.
    if (done) {
        xc[s] = p;                                 // single scalar store
        int gb = (s + 1) & ~3;                     // base of group holding s+1
        if ((s + 1) & 3) {                         // partial group exists
            float4 q = *(const float4*)(xc + gb);  // mixed in/out; out never read
            float xs[4] = {q.x, q.y, q.z, q.w};
            #pragma unroll
            for (int j = 0; j < 4; ++j) {
                int idx = gb + j;
                if (idx > s && idx < CL) {
                    float lo, upx, ub, v1;
                    mkconst(w, xs[j], lo, upx, ub, v1);
                    p = step1(p, lo, upx, ub, v1, w.k_up);
                    xc[idx] = p;
                }
            }
            gb += 4;
        }
        #pragma unroll 1
        for (int u = gb; u < CL; u += 4) {
            float4 q = *(const float4*)(xc + u);
            float lo, upx, ub, v1;
            mkconst(w, q.x, lo, upx, ub, v1);
            float o0 = step1(p,  lo, upx, ub, v1, w.k_up);
            mkconst(w, q.y, lo, upx, ub, v1);
            float o1 = step1(o0, lo, upx, ub, v1, w.k_up);
            mkconst(w, q.z, lo, upx, ub, v1);
            float o2 = step1(o1, lo, upx, ub, v1, w.k_up);
            mkconst(w, q.w, lo, upx, ub, v1);
            float o3 = step1(o2, lo, upx, ub, v1, w.k_up);
            p = o3;
            *(float4*)(xc + u) = make_float4(o0, o1, o2, o3);
        }
    }

    // ---- Phase 2: inter-chunk resolution (pad-slot side channel) ----
    xc[16] = p;                                  // collapsed end value
    reinterpret_cast<int*>(xc)[17] = s;          // collapse index
    bool all = (bool)__syncthreads_and((int)done);   // block-uniform barrier
    float pin;
    if (all) {
        pin = (k == 0) ? p0v : s_buf[(k - 1) * PAD + 16];
    } else {
        if (k == 0) {                             // rare serial fallback
            float prev = p0v;
            for (int c = 0; c < NT; ++c) {
                float* xr = s_buf + c * PAD;
                xr[18] = prev;
                if (reinterpret_cast<int*>(xr)[17] < CL) {
                    prev = xr[16];
                } else {                          // chunk input untouched
                    for (int tt = 0; tt < CL; ++tt) {
                        float lo, upx, ub, v1;
                        mkconst(w, xr[tt], lo, upx, ub, v1);
                        prev = step1(prev, lo, upx, ub, v1, w.k_up);
                    }
                }
            }
        }
        __syncthreads();
        pin = xc[18];
    }

    // ---- Phase 3: replay pre-collapse prefix, vectorized SMEM access ----
    // Group loads are safe: elements with idx >= s are outputs, never consumed.
    #pragma unroll 1
    for (int t4 = 0; t4 < s; t4 += 4) {
        float4 q = *(const float4*)(xc + t4);
        float xs[4] = {q.x, q.y, q.z, q.w};
        float ov[4];
        #pragma unroll
        for (int j = 0; j < 4; ++j) {
            if (t4 + j < s) {
                float lo, upx, ub, v1;
                mkconst(w, xs[j], lo, upx, ub, v1);
                pin = step1(pin, lo, upx, ub, v1, w.k_up);
            }
            ov[j] = pin;              // idx >= s lanes: value unused
        }
        if (t4 + 4 <= s) {            // full group -> conflict-free STS.128
            *(float4*)(xc + t4) = make_float4(ov[0], ov[1], ov[2], ov[3]);
        } else {                      // final partial group -> scalar stores
            #pragma unroll
            for (int j = 0; j < 4; ++j)
                if (t4 + j < s) xc[t4 + j] = ov[j];
        }
    }

    // ---- Warp-local coalesced store: warp w's chunks are final once its own
    //      lanes finish phase 3 (no block barrier needed) ----
    __syncwarp();
    {
        float* dst = out + rowbase + wid * WREG;
        #pragma unroll
        for (int i = 0; i < 4; ++i) {
            int tl = i * 128 + lane * 4;
            int c  = wid * 32 + (tl >> 4);
            int o  = tl & 15;
            float4 v = *(const float4*)(s_buf + c * PAD + o);
            *(float4*)(dst + tl) = v;
        }
    }
}

extern "C" void kernel_launch(void* const* d_in, const int* in_sizes, int n_in,
                              void* d_out, int out_size)
{
    const float* x  = (const float*)d_in[0];  // (B, T, 1) fp32
    const float* p0 = (const float*)d_in[1];  // (B, 1, 1) fp32
    const float* wv = (const float*)d_in[2];  // (4,)      fp32
    float* out = (float*)d_out;

    const int B = in_sizes[1];      // 2048
    const int T = in_sizes[0] / B;  // 8192  (= NT * CL)

    backlash_chunks<<<B, NT>>>(x, p0, wv, out, T);
}

// round 17
// speedup vs baseline: 1.0756x; 1.0580x over previous
#include <cuda_runtime.h>
#include <cstdint>
#include <cstddef>

// BacklashNet chunk-parallel scan: warp-decoupled SMEM staging, interval collapse.
//   lo = fl(fl(m_lo*x) + fl(m_lo*c_lo)), upx = fl(m_up*x), ub = fl(upx + k_up)
//   f1 = (prev >= lo);  f2 = (fl(prev - upx) <= k_up)
//   out = f1 ? (f2 ? fl(fl(lo+upx)+k_up) : lo) : (f2 ? ub : prev)
// Identity branch needs prev in (ub*, lo): interval-tracked until it provably
// collapses to one value -> chunk outputs become state-independent.
// Per-step constants (lo,upx,ub,v1) are element-independent -> computed two
// elements at a time with f32x2 packed ops (bit-identical .rn per lane).

#define NT   512          // threads per block = chunks per row
#define CL   16           // steps per chunk (T = NT*CL = 8192)
#define PAD  20           // smem floats per chunk: 80B stride, 16B aligned;
                          //   conflict-free for 128-bit LDS/STS; slots [16..19]
#define WREG 512          // floats per warp region (32 lanes * CL)

struct Wt { float m_lo, m_up, k_lo, k_up; };

__device__ __forceinline__ uint32_t smem_u32(const void* p) {
    return (uint32_t)__cvta_generic_to_shared(p);
}
__device__ __forceinline__ void cp_async16(uint32_t dst, const float* src) {
    asm volatile("cp.async.ca.shared.global [%0], [%1], 16;\n" :: "r"(dst), "l"(src));
}

__device__ __forceinline__ bool f2_pred(float p, float upx, float k_up) {
    return __fadd_rn(p, -upx) <= k_up;          // fl(p - upx) <= k_up (monotone in p)
}
__device__ __forceinline__ void mkconst(const Wt& w, float xv,
                                        float& lo, float& upx, float& ub, float& v1) {
    float mlx = __fmul_rn(w.m_lo, xv);
    upx = __fmul_rn(w.m_up, xv);
    lo  = __fadd_rn(mlx, w.k_lo);
    ub  = __fadd_rn(upx, w.k_up);
    v1  = __fadd_rn(__fadd_rn(lo, upx), w.k_up); // reference's left-assoc sum
}
// Packed dual-element mkconst: per-lane .rn identical to the scalar version.
__device__ __forceinline__ void mkconst2(
    unsigned long long mlo2, unsigned long long mup2,
    unsigned long long klo2, unsigned long long kup2,
    float xa, float xb,
    float& loa, float& upxa, float& uba, float& v1a,
    float& lob, float& upxb, float& ubb, float& v1b)
{
    unsigned long long X, MLX, UPX, LO, UB, S, V1;
    asm("mov.b64 %0, {%1, %2};"     : "=l"(X)   : "f"(xa), "f"(xb));
    asm("mul.rn.f32x2 %0, %1, %2;"  : "=l"(MLX) : "l"(mlo2), "l"(X));
    asm("mul.rn.f32x2 %0, %1, %2;"  : "=l"(UPX) : "l"(mup2), "l"(X));
    asm("add.rn.f32x2 %0, %1, %2;"  : "=l"(LO)  : "l"(MLX), "l"(klo2));
    asm("add.rn.f32x2 %0, %1, %2;"  : "=l"(UB)  : "l"(UPX), "l"(kup2));
    asm("add.rn.f32x2 %0, %1, %2;"  : "=l"(S)   : "l"(LO),  "l"(UPX));
    asm("add.rn.f32x2 %0, %1, %2;"  : "=l"(V1)  : "l"(S),   "l"(kup2));
    asm("mov.b64 {%0, %1}, %2;" : "=f"(loa),  "=f"(lob)  : "l"(LO));
    asm("mov.b64 {%0, %1}, %2;" : "=f"(upxa), "=f"(upxb) : "l"(UPX));
    asm("mov.b64 {%0, %1}, %2;" : "=f"(uba),  "=f"(ubb)  : "l"(UB));
    asm("mov.b64 {%0, %1}, %2;" : "=f"(v1a),  "=f"(v1b)  : "l"(V1));
}
__device__ __forceinline__ float step1(float p, float lo, float upx, float ub,
                                       float v1, float k_up) {
    bool f1 = (p >= lo);
    bool f2 = f2_pred(p, upx, k_up);
    float a = f2 ? v1 : lo;
    float b = f2 ? ub : p;
    return f1 ? a : b;
}

__global__ __launch_bounds__(NT, 3)
void backlash_chunks(const float* __restrict__ x,
                     const float* __restrict__ p0,
                     const float* __restrict__ wv,
                     float* __restrict__ out, int T)
{
    __shared__ float s_buf[NT * PAD];   // chunk data + pad slots:
                                        //   xc[16]=cv  xc[17]=sx(int)  xc[18]=in

    const int k    = threadIdx.x;
    const int wid  = k >> 5;            // warp id (0..15)
    const int lane = k & 31;

    Wt w;
    w.m_lo = wv[0];
    w.m_up = wv[1];
    w.k_lo = __fmul_rn(w.m_lo, wv[2]);
    w.k_up = __fmul_rn(w.m_up, wv[3]);

    // Broadcast pairs for packed mkconst2.
    unsigned long long mlo2, mup2, klo2, kup2;
    asm("mov.b64 %0, {%1, %2};" : "=l"(mlo2) : "f"(w.m_lo), "f"(w.m_lo));
    asm("mov.b64 %0, {%1, %2};" : "=l"(mup2) : "f"(w.m_up), "f"(w.m_up));
    asm("mov.b64 %0, {%1, %2};" : "=l"(klo2) : "f"(w.k_lo), "f"(w.k_lo));
    asm("mov.b64 %0, {%1, %2};" : "=l"(kup2) : "f"(w.k_up), "f"(w.k_up));

    const size_t rowbase = (size_t)blockIdx.x * T;

    // ---- Warp-local coalesced staged load: warp w owns chunks [32w, 32w+32) ----
    {
        const float* src = x + rowbase + wid * WREG;
        const uint32_t sb = smem_u32(s_buf);
        #pragma unroll
        for (int i = 0; i < 4; ++i) {
            int tl = i * 128 + lane * 4;            // [0, 512) within warp region
            int c  = wid * 32 + (tl >> 4);
            int o  = tl & 15;
            cp_async16(sb + (uint32_t)(c * PAD + o) * 4u, src + tl);
        }
        asm volatile("cp.async.commit_group;\n" ::: "memory");
        asm volatile("cp.async.wait_group 0;\n" ::: "memory");
        __syncwarp();   // make cp.async data visible across the warp's lanes
    }

    float* xc = s_buf + k * PAD;        // this thread's chunk (in; becomes out)
    const float INF = __int_as_float(0x7f800000);

    // ---- Phase 1a: interval scan until collapse (float4 group loads, no stores) ----
    float A = -INF, Bv = INF;
    float p = 0.0f;
    bool  done = false;
    int   s = CL;

    #pragma unroll 1
    for (int t4 = 0; t4 < CL && !done; t4 += 4) {
        float4 q = *(const float4*)(xc + t4);
        float xs[4] = {q.x, q.y, q.z, q.w};
        #pragma unroll
        for (int j = 0; j < 4; ++j) {
            if (!done) {
                float lo, upx, ub, v1;
                mkconst(w, xs[j], lo, upx, ub, v1);
                // Region reachability over [A,Bv] via exact predicate evals.
                // ps = fminf(Bv, lo): conservative (<=1 ulp) identity hull top;
                // survival test at ps can only over-keep (sound).
                float mAlo = fmaxf(A, lo);
                float ps   = fminf(Bv, lo);
                bool aL = (A < lo);
                bool c1 = (mAlo <= Bv) &&  f2_pred(mAlo, upx, w.k_up); // f1& f2 -> v1
                bool c2 = (Bv >= lo)   && !f2_pred(Bv,   upx, w.k_up); // f1&!f2 -> lo
                bool c3 = aL           &&  f2_pred(A,    upx, w.k_up); //!f1& f2 -> ub
                bool c4 = aL           && !f2_pred(ps,   upx, w.k_up); // identity
                float nA = INF, nB = -INF;
                if (c1) { nA = fminf(nA, v1); nB = fmaxf(nB, v1); }
                if (c2) { nA = fminf(nA, lo); nB = fmaxf(nB, lo); }
                if (c3) { nA = fminf(nA, ub); nB = fmaxf(nB, ub); }
                if (c4) { nA = fminf(nA, A);  nB = fmaxf(nB, ps); }
                A = nA; Bv = nB;
                if (A == Bv) { done = true; p = A; s = t4 + j; }
            }
        }
    }

    // ---- Phase 1b: concrete scan, in-place stores for t >= s ----
    // Partial group (contains s..): one conflict-free LDS.128, predicated scalar
    // stores only for indices in (s, group end). Inputs at idx < s stay intact.
    if (done) {
        xc[s] = p;                                 // single scalar store
        int gb = (s + 1) & ~3;                     // base of group holding s+1
        if ((s + 1) & 3) {                         // partial group exists
            float4 q = *(const float4*)(xc + gb);  // mixed in/out; out never read
            float xs[4] = {q.x, q.y, q.z, q.w};
            #pragma unroll
            for (int j = 0; j < 4; ++j) {
                int idx = gb + j;
                if (idx > s && idx < CL) {
                    float lo, upx, ub, v1;
                    mkconst(w, xs[j], lo, upx, ub, v1);
                    p = step1(p, lo, upx, ub, v1, w.k_up);
                    xc[idx] = p;
                }
            }
            gb += 4;
        }
        #pragma unroll 1
        for (int u = gb; u < CL; u += 4) {
            float4 q = *(const float4*)(xc + u);
            float lo0,upx0,ub0,v10, lo1,upx1,ub1,v11;
            mkconst2(mlo2, mup2, klo2, kup2, q.x, q.y,
                     lo0, upx0, ub0, v10, lo1, upx1, ub1, v11);
            float o0 = step1(p,  lo0, upx0, ub0, v10, w.k_up);
            float o1 = step1(o0, lo1, upx1, ub1, v11, w.k_up);
            float lo2,upx2,ub2,v12, lo3,upx3,ub3,v13;
            mkconst2(mlo2, mup2, klo2, kup2, q.z, q.w,
                     lo2, upx2, ub2, v12, lo3, upx3, ub3, v13);
            float o2 = step1(o1, lo2, upx2, ub2, v12, w.k_up);
            float o3 = step1(o2, lo3, upx3, ub3, v13, w.k_up);
            p = o3;
            *(float4*)(xc + u) = make_float4(o0, o1, o2, o3);
        }
    }

    // ---- Phase 2: inter-chunk resolution (pad-slot side channel) ----
    xc[16] = p;                                  // collapsed end value
    reinterpret_cast<int*>(xc)[17] = s;          // collapse index
    bool all = (bool)__syncthreads_and((int)done);   // block-uniform barrier
    float pin;
    if (all) {
        pin = (k == 0) ? p0[blockIdx.x] : s_buf[(k - 1) * PAD + 16];
    } else {
        if (k == 0) {                             // rare serial fallback
            float prev = p0[blockIdx.x];
            for (int c = 0; c < NT; ++c) {
                float* xr = s_buf + c * PAD;
                xr[18] = prev;
                if (reinterpret_cast<int*>(xr)[17] < CL) {
                    prev = xr[16];
                } else {                          // chunk input untouched
                    for (int tt = 0; tt < CL; ++tt) {
                        float lo, upx, ub, v1;
                        mkconst(w, xr[tt], lo, upx, ub, v1);
                        prev = step1(prev, lo, upx, ub, v1, w.k_up);
                    }
                }
            }
        }
        __syncthreads();
        pin = xc[18];
    }

    // ---- Phase 3: replay pre-collapse prefix, vectorized SMEM access ----
    // Group loads are safe: elements with idx >= s are outputs, never consumed.
    // mkconst2 runs unconditionally per pair (pure arithmetic; unused lanes ok).
    #pragma unroll 1
    for (int t4 = 0; t4 < s; t4 += 4) {
        float4 q = *(const float4*)(xc + t4);
        float ov[4];
        float lo0,upx0,ub0,v10, lo1,upx1,ub1,v11;
        mkconst2(mlo2, mup2, klo2, kup2, q.x, q.y,
                 lo0, upx0, ub0, v10, lo1, upx1, ub1, v11);
        if (t4 + 0 < s) pin = step1(pin, lo0, upx0, ub0, v10, w.k_up);
        ov[0] = pin;
        if (t4 + 1 < s) pin = step1(pin, lo1, upx1, ub1, v11, w.k_up);
        ov[1] = pin;
        float lo2,upx2,ub2,v12, lo3,upx3,ub3,v13;
        mkconst2(mlo2, mup2, klo2, kup2, q.z, q.w,
                 lo2, upx2, ub2, v12, lo3, upx3, ub3, v13);
        if (t4 + 2 < s) pin = step1(pin, lo2, upx2, ub2, v12, w.k_up);
        ov[2] = pin;
        if (t4 + 3 < s) pin = step1(pin, lo3, upx3, ub3, v13, w.k_up);
        ov[3] = pin;
        if (t4 + 4 <= s) {            // full group -> conflict-free STS.128
            *(float4*)(xc + t4) = make_float4(ov[0], ov[1], ov[2], ov[3]);
        } else {                      // final partial group -> scalar stores
            #pragma unroll
            for (int j = 0; j < 4; ++j)
                if (t4 + j < s) xc[t4 + j] = ov[j];
        }
    }

    // ---- Warp-local coalesced store: warp w's chunks are final once its own
    //      lanes finish phase 3 (no block barrier needed) ----
    __syncwarp();
    {
        float* dst = out + rowbase + wid * WREG;
        #pragma unroll
        for (int i = 0; i < 4; ++i) {
            int tl = i * 128 + lane * 4;
            int c  = wid * 32 + (tl >> 4);
            int o  = tl & 15;
            float4 v = *(const float4*)(s_buf + c * PAD + o);
            *(float4*)(dst + tl) = v;
        }
    }
}

extern "C" void kernel_launch(void* const* d_in, const int* in_sizes, int n_in,
                              void* d_out, int out_size)
{
    const float* x  = (const float*)d_in[0];  // (B, T, 1) fp32
    const float* p0 = (const float*)d_in[1];  // (B, 1, 1) fp32
    const float* wv = (const float*)d_in[2];  // (4,)      fp32
    float* out = (float*)d_out;

    const int B = in_sizes[1];      // 2048
    const int T = in_sizes[0] / B;  // 8192  (= NT * CL)

    backlash_chunks<<<B, NT>>>(x, p0, wv, out, T);
}